// round 1
// baseline (speedup 1.0000x reference)
#include <cuda_runtime.h>
#include <cuda_bf16.h>
#include <math.h>

// Problem constants
#define BB   32
#define NN   1024
#define CIN  64
#define CO   128
#define KNN  16
#define BNROWS (BB*NN)          // 32768
#define ROWS   (BNROWS*KNN)     // 524288
#define GEMM_BLOCKS (ROWS/128)  // 4096
#define EPSV 1e-5f

typedef unsigned long long ull;

// ------------------------- device scratch (static, no allocs) ----------------
static __device__ int   g_idx[ROWS];                  // 2 MB  (bn,k) -> neighbor n
static __device__ float g_center[BNROWS*CO];          // 16 MB
static __device__ float g_h[BNROWS*CO];               // 16 MB
static __device__ float g_sc[BNROWS*CO];              // 16 MB
static __device__ float g_x0[(size_t)ROWS*CO];        // 268 MB
static __device__ float g_x1[(size_t)ROWS*CO];        // 268 MB
static __device__ float g_part[GEMM_BLOCKS*256];      // 4 MB
static __device__ float g_coef[4*256];                // (a[128],d[128]) x4

// ------------------------- helpers -------------------------------------------
__device__ __forceinline__ void ffma2(ull& d, ull a, ull b) {
    asm("fma.rn.f32x2 %0, %1, %2, %0;" : "+l"(d) : "l"(a), "l"(b));
}
__device__ __forceinline__ ull dup2(float w) {
    ull r; asm("mov.b64 %0, {%1, %1};" : "=l"(r) : "f"(w)); return r;
}
__device__ __forceinline__ void unpack2(ull v, float& lo, float& hi) {
    asm("mov.b64 {%0, %1}, %2;" : "=f"(lo), "=f"(hi) : "l"(v));
}

// ------------------------- 1) kNN --------------------------------------------
// one block per query point; dist = 2*inner - xx_n - xx_m (matches reference),
// 16 rounds of block-wide argmax (tie -> smaller index), self excluded.
__global__ void knn_kernel(const float* __restrict__ pts, int* __restrict__ idxout) {
    __shared__ float dist[NN];
    __shared__ float rv[256];
    __shared__ int   ri[256];
    int q = blockIdx.x;
    int b = q >> 10, n = q & 1023;
    const float* P = pts + (size_t)b * 3 * NN;
    int t = threadIdx.x;
    float qx = P[n], qy = P[NN + n], qz = P[2*NN + n];
    float xxq = qx*qx + qy*qy + qz*qz;
    for (int m = t; m < NN; m += 256) {
        float px = P[m], py = P[NN + m], pz = P[2*NN + m];
        float xxm = px*px + py*py + pz*pz;
        float inn = qx*px + qy*py + qz*pz;
        float d = 2.f*inn - xxq - xxm;
        dist[m] = (m == n) ? -INFINITY : d;
    }
    __syncthreads();
    for (int r = 0; r < KNN; r++) {
        float bv = -INFINITY; int bi = 0x3fffffff;
        for (int m = t; m < NN; m += 256) {
            float d = dist[m];
            if (d > bv) { bv = d; bi = m; }   // first-seen wins on ties (smaller m)
        }
        rv[t] = bv; ri[t] = bi;
        __syncthreads();
        for (int s = 128; s > 0; s >>= 1) {
            if (t < s) {
                float ov = rv[t + s]; int oi = ri[t + s];
                if (ov > rv[t] || (ov == rv[t] && oi < ri[t])) { rv[t] = ov; ri[t] = oi; }
            }
            __syncthreads();
        }
        if (t == 0) { idxout[q*KNN + r] = ri[0]; dist[ri[0]] = -INFINITY; }
        __syncthreads();
    }
}

// ------------------------- 2) per-point GEMVs --------------------------------
// center = f^T (W0a - W0b)^T ; h = f^T W0b^T ; sc = f^T Wsc^T
__global__ void feat_kernel(const float* __restrict__ f,
                            const float* __restrict__ W0,
                            const float* __restrict__ Wsc,
                            float* __restrict__ center,
                            float* __restrict__ h,
                            float* __restrict__ sc) {
    __shared__ float fs[CIN][16];
    int base = blockIdx.x * 16;
    int b = base >> 10, n0 = base & 1023;
    int t = threadIdx.x;
    #pragma unroll
    for (int i = 0; i < 8; i++) {
        int idx = t + 128*i;
        int c = idx >> 4, j = idx & 15;
        fs[c][j] = f[(size_t)b*CIN*NN + c*NN + n0 + j];
    }
    __syncthreads();
    int o = t;
    float ctr[16], hh[16], ss[16];
    #pragma unroll
    for (int j = 0; j < 16; j++) { ctr[j]=0.f; hh[j]=0.f; ss[j]=0.f; }
    for (int c = 0; c < CIN; c++) {
        float w0a = W0[o*128 + c];
        float w0b = W0[o*128 + 64 + c];
        float ws  = Wsc[o*64 + c];
        float wc  = w0a - w0b;
        const float* fr = fs[c];
        #pragma unroll
        for (int j = 0; j < 16; j++) {
            float fv = fr[j];
            ctr[j] = fmaf(wc,  fv, ctr[j]);
            hh[j]  = fmaf(w0b, fv, hh[j]);
            ss[j]  = fmaf(ws,  fv, ss[j]);
        }
    }
    #pragma unroll
    for (int j = 0; j < 16; j++) {
        int row = base + j;
        center[row*CO + o] = ctr[j];
        h[row*CO + o]      = hh[j];
        sc[row*CO + o]     = ss[j];
    }
}

// ------------------------- 3) build layer-0 output + stats partials ----------
__global__ void build_kernel(const float* __restrict__ center,
                             const float* __restrict__ h,
                             const int* __restrict__ idx,
                             float* __restrict__ x0,
                             float* __restrict__ part) {
    __shared__ float red[8][132];
    int t = threadIdx.x;
    int oq = (t & 31) << 2;       // channel quad
    int strip = t >> 5;           // 0..7 -> one (b,n) per strip
    int bn = blockIdx.x * 8 + strip;
    int b = bn >> 10;
    float4 c4 = *reinterpret_cast<const float4*>(&center[bn*CO + oq]);
    const int* ip = idx + bn*KNN;
    float s0=0,s1=0,s2=0,s3=0, q0=0,q1=0,q2=0,q3=0;
    #pragma unroll
    for (int k = 0; k < KNN; k++) {
        int gi = ip[k];
        float4 h4 = *reinterpret_cast<const float4*>(&h[(b*NN + gi)*CO + oq]);
        float4 v;
        v.x = c4.x + h4.x; v.y = c4.y + h4.y; v.z = c4.z + h4.z; v.w = c4.w + h4.w;
        *reinterpret_cast<float4*>(&x0[(size_t)(bn*KNN + k)*CO + oq]) = v;
        s0 += v.x; s1 += v.y; s2 += v.z; s3 += v.w;
        q0 = fmaf(v.x,v.x,q0); q1 = fmaf(v.y,v.y,q1); q2 = fmaf(v.z,v.z,q2); q3 = fmaf(v.w,v.w,q3);
    }
    red[strip][oq+0]=s0; red[strip][oq+1]=s1; red[strip][oq+2]=s2; red[strip][oq+3]=s3;
    __syncthreads();
    if (t < 128) {
        float s = 0;
        #pragma unroll
        for (int q = 0; q < 8; q++) s += red[q][t];
        part[blockIdx.x*256 + t] = s;
    }
    __syncthreads();
    red[strip][oq+0]=q0; red[strip][oq+1]=q1; red[strip][oq+2]=q2; red[strip][oq+3]=q3;
    __syncthreads();
    if (t < 128) {
        float s = 0;
        #pragma unroll
        for (int q = 0; q < 8; q++) s += red[q][t];
        part[blockIdx.x*256 + 128 + t] = s;
    }
}

// ------------------------- 4) stats: partials -> (a, d) ----------------------
__global__ void stats_kernel(const float* __restrict__ part, int nparts,
                             const float* __restrict__ g, const float* __restrict__ bt,
                             float* __restrict__ coef, float invM) {
    __shared__ float ss[256], qq[256];
    int o = blockIdx.x, t = threadIdx.x;
    float s = 0.f, q = 0.f;
    for (int p = t; p < nparts; p += 256) {
        s += part[p*256 + o];
        q += part[p*256 + 128 + o];
    }
    ss[t] = s; qq[t] = q;
    __syncthreads();
    for (int st = 128; st > 0; st >>= 1) {
        if (t < st) { ss[t] += ss[t+st]; qq[t] += qq[t+st]; }
        __syncthreads();
    }
    if (t == 0) {
        float mean = ss[0] * invM;
        float var  = qq[0] * invM - mean*mean;
        float a = g[o] / sqrtf(var + EPSV);
        coef[o] = a;
        coef[128 + o] = bt[o] - mean * a;
    }
}

// column stats directly over a (rows x 128) tensor (shortcut path)
__global__ void colstats_kernel(const float* __restrict__ X, int rows,
                                const float* __restrict__ g, const float* __restrict__ bt,
                                float* __restrict__ coef) {
    __shared__ float ss[256], qq[256];
    int o = blockIdx.x, t = threadIdx.x;
    float s = 0.f, q = 0.f;
    for (int r = t; r < rows; r += 256) {
        float v = X[(size_t)r*CO + o];
        s += v; q = fmaf(v, v, q);
    }
    ss[t] = s; qq[t] = q;
    __syncthreads();
    for (int st = 128; st > 0; st >>= 1) {
        if (t < st) { ss[t] += ss[t+st]; qq[t] += qq[t+st]; }
        __syncthreads();
    }
    if (t == 0) {
        float invM = 1.f / (float)rows;
        float mean = ss[0] * invM;
        float var  = qq[0] * invM - mean*mean;
        float a = g[o] / sqrtf(var + EPSV);
        coef[o] = a;
        coef[128 + o] = bt[o] - mean * a;
    }
}

// ------------------------- 5) fused act(prev BN)+GEMM + stats ----------------
// Y[m,o] = sum_c W[o,c] * relu(a_c * X[m,c] + d_c); emits per-block channel partials.
// Packed f32x2 FMAs, B pre-duplicated in SMEM.
__global__ __launch_bounds__(256, 2)
void gemm_kernel(const float* __restrict__ X, const float* __restrict__ W,
                 const float* __restrict__ coef, float* __restrict__ Y,
                 float* __restrict__ part) {
    __shared__ __align__(16) float As[16][132];
    __shared__ __align__(16) ull   Bs[16][128];
    __shared__ float sa[128], sd[128];
    __shared__ float red[16][128];
    int t = threadIdx.x;
    if (t < 128) { sa[t] = coef[t]; sd[t] = coef[128 + t]; }
    __syncthreads();
    int tx = t & 15, ty = t >> 4;
    int m0 = ty * 8, o0 = tx * 8;
    size_t mbase = (size_t)blockIdx.x * 128;

    ull acc[8][4];
    #pragma unroll
    for (int j = 0; j < 8; j++)
        #pragma unroll
        for (int ip = 0; ip < 4; ip++) acc[j][ip] = 0ULL;

    for (int kb = 0; kb < 8; kb++) {
        int cbase = kb * 16;
        #pragma unroll
        for (int i = 0; i < 8; i++) {
            int idx = t + 256*i;
            int c = idx & 15, m = idx >> 4;
            float x = X[(mbase + m)*CO + cbase + c];
            As[c][m] = fmaxf(fmaf(sa[cbase + c], x, sd[cbase + c]), 0.f);
        }
        #pragma unroll
        for (int i = 0; i < 8; i++) {
            int idx = t + 256*i;
            int c = idx & 15, o = idx >> 4;
            Bs[c][o] = dup2(W[o*CO + cbase + c]);
        }
        __syncthreads();
        #pragma unroll
        for (int k = 0; k < 16; k++) {
            ulonglong2 a01 = *reinterpret_cast<const ulonglong2*>(&As[k][m0]);
            ulonglong2 a23 = *reinterpret_cast<const ulonglong2*>(&As[k][m0 + 4]);
            ull av0 = a01.x, av1 = a01.y, av2 = a23.x, av3 = a23.y;
            const ulonglong2* bp = reinterpret_cast<const ulonglong2*>(&Bs[k][o0]);
            ulonglong2 b01 = bp[0], b23 = bp[1], b45 = bp[2], b67 = bp[3];
            ull bv[8] = {b01.x, b01.y, b23.x, b23.y, b45.x, b45.y, b67.x, b67.y};
            #pragma unroll
            for (int j = 0; j < 8; j++) {
                ffma2(acc[j][0], av0, bv[j]);
                ffma2(acc[j][1], av1, bv[j]);
                ffma2(acc[j][2], av2, bv[j]);
                ffma2(acc[j][3], av3, bv[j]);
            }
        }
        __syncthreads();
    }

    float ysum[8], ysq[8];
    #pragma unroll
    for (int j = 0; j < 8; j++) { ysum[j] = 0.f; ysq[j] = 0.f; }
    #pragma unroll
    for (int ip = 0; ip < 4; ip++) {
        float lo[8], hi[8];
        #pragma unroll
        for (int j = 0; j < 8; j++) unpack2(acc[j][ip], lo[j], hi[j]);
        size_t row = mbase + m0 + 2*ip;
        float4* d0 = reinterpret_cast<float4*>(&Y[row*CO + o0]);
        d0[0] = make_float4(lo[0], lo[1], lo[2], lo[3]);
        d0[1] = make_float4(lo[4], lo[5], lo[6], lo[7]);
        float4* d1 = reinterpret_cast<float4*>(&Y[(row + 1)*CO + o0]);
        d1[0] = make_float4(hi[0], hi[1], hi[2], hi[3]);
        d1[1] = make_float4(hi[4], hi[5], hi[6], hi[7]);
        #pragma unroll
        for (int j = 0; j < 8; j++) {
            ysum[j] += lo[j] + hi[j];
            ysq[j]  = fmaf(lo[j], lo[j], fmaf(hi[j], hi[j], ysq[j]));
        }
    }
    #pragma unroll
    for (int j = 0; j < 8; j++) red[ty][o0 + j] = ysum[j];
    __syncthreads();
    if (t < 128) {
        float s = 0;
        #pragma unroll
        for (int q = 0; q < 16; q++) s += red[q][t];
        part[blockIdx.x*256 + t] = s;
    }
    __syncthreads();
    #pragma unroll
    for (int j = 0; j < 8; j++) red[ty][o0 + j] = ysq[j];
    __syncthreads();
    if (t < 128) {
        float s = 0;
        #pragma unroll
        for (int q = 0; q < 16; q++) s += red[q][t];
        part[blockIdx.x*256 + 128 + t] = s;
    }
}

// ------------------------- 6) final: mean_k relu(bn2) + bn_sc + relu, transpose
__global__ void final_kernel(const float* __restrict__ x2, const float* __restrict__ sc,
                             const float* __restrict__ coef2, const float* __restrict__ coefsc,
                             float* __restrict__ out) {
    int bn = blockIdx.x;
    int o = threadIdx.x;
    float a2 = coef2[o], d2 = coef2[128 + o];
    float as = coefsc[o], ds = coefsc[128 + o];
    const float* xr = x2 + (size_t)bn * KNN * CO + o;
    float s = 0.f;
    #pragma unroll
    for (int k = 0; k < KNN; k++)
        s += fmaxf(fmaf(a2, xr[k*CO], d2), 0.f);
    float scv = sc[bn*CO + o];
    float val = fmaxf(fmaf(as, scv, ds) + s * (1.f/16.f), 0.f);
    int b = bn >> 10, n = bn & 1023;
    out[(size_t)b*CO*NN + o*NN + n] = val;
}

// ------------------------- host launcher -------------------------------------
extern "C" void kernel_launch(void* const* d_in, const int* in_sizes, int n_in,
                              void* d_out, int out_size) {
    const float* points   = (const float*)d_in[0];
    const float* features = (const float*)d_in[1];
    const float* W0  = (const float*)d_in[2];
    const float* g0  = (const float*)d_in[3];
    const float* b0  = (const float*)d_in[4];
    const float* W1  = (const float*)d_in[5];
    const float* g1  = (const float*)d_in[6];
    const float* b1  = (const float*)d_in[7];
    const float* W2  = (const float*)d_in[8];
    const float* g2  = (const float*)d_in[9];
    const float* b2  = (const float*)d_in[10];
    const float* Wsc = (const float*)d_in[11];
    const float* gsc = (const float*)d_in[12];
    const float* bsc = (const float*)d_in[13];
    float* out = (float*)d_out;

    void *p_idx, *p_center, *p_h, *p_sc, *p_x0, *p_x1, *p_part, *p_coef;
    cudaGetSymbolAddress(&p_idx,    g_idx);
    cudaGetSymbolAddress(&p_center, g_center);
    cudaGetSymbolAddress(&p_h,      g_h);
    cudaGetSymbolAddress(&p_sc,     g_sc);
    cudaGetSymbolAddress(&p_x0,     g_x0);
    cudaGetSymbolAddress(&p_x1,     g_x1);
    cudaGetSymbolAddress(&p_part,   g_part);
    cudaGetSymbolAddress(&p_coef,   g_coef);

    int*   idx    = (int*)p_idx;
    float* center = (float*)p_center;
    float* h      = (float*)p_h;
    float* sc     = (float*)p_sc;
    float* x0     = (float*)p_x0;
    float* x1     = (float*)p_x1;
    float* part   = (float*)p_part;
    float* coef0  = (float*)p_coef;
    float* coef1  = coef0 + 256;
    float* coef2  = coef0 + 512;
    float* coef3  = coef0 + 768;

    const float invM = 1.f / (float)ROWS;

    knn_kernel<<<BNROWS, 256>>>(points, idx);
    feat_kernel<<<BNROWS/16, 128>>>(features, W0, Wsc, center, h, sc);
    build_kernel<<<GEMM_BLOCKS, 256>>>(center, h, idx, x0, part);
    stats_kernel<<<128, 256>>>(part, GEMM_BLOCKS, g0, b0, coef0, invM);
    gemm_kernel<<<GEMM_BLOCKS, 256>>>(x0, W1, coef0, x1, part);
    stats_kernel<<<128, 256>>>(part, GEMM_BLOCKS, g1, b1, coef1, invM);
    gemm_kernel<<<GEMM_BLOCKS, 256>>>(x1, W2, coef1, x0, part);
    stats_kernel<<<128, 256>>>(part, GEMM_BLOCKS, g2, b2, coef2, invM);
    colstats_kernel<<<128, 256>>>(sc, BNROWS, gsc, bsc, coef3);
    final_kernel<<<BNROWS, 128>>>(x0, sc, coef2, coef3, out);
}